// round 1
// baseline (speedup 1.0000x reference)
#include <cuda_runtime.h>

#define Bb 2
#define Ss 2048
#define Ee 1024
#define Hh 16
#define Dd 64
#define Mrows (Bb*Ss)

// Scratch (allocation-free rule: device globals)
__device__ float g_qh[Bb*Hh*Ss*Dd];   // [B,H,S,D]
__device__ float g_kh[Bb*Hh*Ss*Dd];
__device__ float g_vh[Bb*Hh*Ss*Dd];
__device__ float g_ao[Bb*Ss*Ee];      // attention out, [B,S,E]

// ---------------------------------------------------------------------------
// Fused QKV projection: out(m,n) = sum_k A[m,k] * W[n,k] + bias[n]
// Tiled 64x64x16, 256 threads, 4x4 microtile. Epilogue scatters to head layout.
// ---------------------------------------------------------------------------
__global__ __launch_bounds__(256) void qkv_kernel(
    const float* __restrict__ qin, const float* __restrict__ kin,
    const float* __restrict__ vin,
    const float* __restrict__ Wq, const float* __restrict__ bq,
    const float* __restrict__ Wk, const float* __restrict__ bk,
    const float* __restrict__ Wv, const float* __restrict__ bv)
{
    const float* A; const float* W; const float* bias; float* dst;
    if (blockIdx.z == 0)      { A = qin; W = Wq; bias = bq; dst = g_qh; }
    else if (blockIdx.z == 1) { A = kin; W = Wk; bias = bk; dst = g_kh; }
    else                      { A = vin; W = Wv; bias = bv; dst = g_vh; }

    __shared__ float As[16][64];
    __shared__ float Bs[16][64];

    const int m0 = blockIdx.y * 64, n0 = blockIdx.x * 64;
    const int tid = threadIdx.x;
    const int ty = tid >> 4, tx = tid & 15;
    const int lm = tid >> 2, lk = (tid & 3) * 4;

    float acc[4][4] = {};

    for (int k0 = 0; k0 < Ee; k0 += 16) {
        float4 av = *(const float4*)(A + (size_t)(m0 + lm) * Ee + k0 + lk);
        float4 wv = *(const float4*)(W + (size_t)(n0 + lm) * Ee + k0 + lk);
        As[lk + 0][lm] = av.x; As[lk + 1][lm] = av.y;
        As[lk + 2][lm] = av.z; As[lk + 3][lm] = av.w;
        Bs[lk + 0][lm] = wv.x; Bs[lk + 1][lm] = wv.y;
        Bs[lk + 2][lm] = wv.z; Bs[lk + 3][lm] = wv.w;
        __syncthreads();
        #pragma unroll
        for (int kk = 0; kk < 16; kk++) {
            float4 a4 = *(const float4*)&As[kk][ty * 4];
            float4 b4 = *(const float4*)&Bs[kk][tx * 4];
            float aa[4] = {a4.x, a4.y, a4.z, a4.w};
            float bb[4] = {b4.x, b4.y, b4.z, b4.w};
            #pragma unroll
            for (int i = 0; i < 4; i++)
                #pragma unroll
                for (int j = 0; j < 4; j++)
                    acc[i][j] = fmaf(aa[i], bb[j], acc[i][j]);
        }
        __syncthreads();
    }

    #pragma unroll
    for (int i = 0; i < 4; i++) {
        int m = m0 + ty * 4 + i;
        int b = m / Ss, s = m % Ss;
        #pragma unroll
        for (int j = 0; j < 4; j++) {
            int n = n0 + tx * 4 + j;
            int h = n >> 6, d = n & 63;
            dst[(((size_t)(b * Hh + h)) * Ss + s) * Dd + d] = acc[i][j] + bias[n];
        }
    }
}

// ---------------------------------------------------------------------------
// Flash attention fp32. One block = one (b,h) x 64-query tile, 256 threads.
// Dynamic smem (64KB): Qs [d][q], Ks [d][k], Vs [k][d], Ps [q][k].
// ---------------------------------------------------------------------------
__global__ __launch_bounds__(256) void attn_kernel(const unsigned char* __restrict__ mask)
{
    extern __shared__ float sm[];
    float* Qs = sm;            // 4096: Qs[d*64+q]
    float* Ks = sm + 4096;     // Ks[d*64+k]
    float* Vs = sm + 8192;     // Vs[k*64+d]
    float* Ps = sm + 12288;    // Ps[q*64+k]
    __shared__ float maskS[64];

    const int bh = blockIdx.y;
    const int b = bh >> 4, h = bh & 15;
    const int q0 = blockIdx.x * 64;
    const int tid = threadIdx.x;
    const int ty = tid >> 4, tx = tid & 15;

    const float* Qg = g_qh + ((size_t)(b * Hh + h) * Ss + q0) * Dd;
    // Load Q tile transposed (d-major)
    #pragma unroll
    for (int it = 0; it < 4; it++) {
        int v = tid + it * 256;          // float4 index, 1024 total
        int row = v >> 4, d0 = (v & 15) * 4;
        float4 x = *(const float4*)(Qg + row * 64 + d0);
        Qs[(d0 + 0) * 64 + row] = x.x; Qs[(d0 + 1) * 64 + row] = x.y;
        Qs[(d0 + 2) * 64 + row] = x.z; Qs[(d0 + 3) * 64 + row] = x.w;
    }

    float m_i[4], l_i[4], o[4][4];
    #pragma unroll
    for (int i = 0; i < 4; i++) {
        m_i[i] = -1e30f; l_i[i] = 0.f;
        #pragma unroll
        for (int j = 0; j < 4; j++) o[i][j] = 0.f;
    }

    const float* Kg0 = g_kh + (size_t)(b * Hh + h) * Ss * Dd;
    const float* Vg0 = g_vh + (size_t)(b * Hh + h) * Ss * Dd;

    for (int t = 0; t < Ss / 64; t++) {
        __syncthreads();   // previous PV done with Vs/Ps
        const float* Kg = Kg0 + t * 64 * 64;
        const float* Vg = Vg0 + t * 64 * 64;
        #pragma unroll
        for (int it = 0; it < 4; it++) {
            int v = tid + it * 256;
            int row = v >> 4, d0 = (v & 15) * 4;
            float4 x = *(const float4*)(Kg + row * 64 + d0);
            Ks[(d0 + 0) * 64 + row] = x.x; Ks[(d0 + 1) * 64 + row] = x.y;
            Ks[(d0 + 2) * 64 + row] = x.z; Ks[(d0 + 3) * 64 + row] = x.w;
            *(float4*)(Vs + v * 4) = *(const float4*)(Vg + v * 4);
        }
        if (tid < 64)
            maskS[tid] = mask[b * Ss + t * 64 + tid] ? -1e30f : 0.0f;
        __syncthreads();

        // Scores: s = 0.125 * Q K^T + mask
        float s[4][4];
        #pragma unroll
        for (int i = 0; i < 4; i++)
            #pragma unroll
            for (int j = 0; j < 4; j++) s[i][j] = 0.f;

        #pragma unroll 8
        for (int d = 0; d < 64; d++) {
            float4 a4 = *(const float4*)&Qs[d * 64 + ty * 4];
            float4 b4 = *(const float4*)&Ks[d * 64 + tx * 4];
            float aa[4] = {a4.x, a4.y, a4.z, a4.w};
            float bb[4] = {b4.x, b4.y, b4.z, b4.w};
            #pragma unroll
            for (int i = 0; i < 4; i++)
                #pragma unroll
                for (int j = 0; j < 4; j++)
                    s[i][j] = fmaf(aa[i], bb[j], s[i][j]);
        }
        #pragma unroll
        for (int i = 0; i < 4; i++)
            #pragma unroll
            for (int j = 0; j < 4; j++)
                s[i][j] = s[i][j] * 0.125f + maskS[tx * 4 + j];

        // Online softmax; row groups = 16 lanes (same ty within warp)
        #pragma unroll
        for (int i = 0; i < 4; i++) {
            float tm = fmaxf(fmaxf(s[i][0], s[i][1]), fmaxf(s[i][2], s[i][3]));
            #pragma unroll
            for (int off = 1; off < 16; off <<= 1)
                tm = fmaxf(tm, __shfl_xor_sync(0xffffffffu, tm, off, 16));
            float mn = fmaxf(m_i[i], tm);
            float factor = __expf(m_i[i] - mn);
            float rs = 0.f;
            #pragma unroll
            for (int j = 0; j < 4; j++) {
                float p = __expf(s[i][j] - mn);
                s[i][j] = p;
                rs += p;
            }
            #pragma unroll
            for (int off = 1; off < 16; off <<= 1)
                rs += __shfl_xor_sync(0xffffffffu, rs, off, 16);
            l_i[i] = l_i[i] * factor + rs;
            m_i[i] = mn;
            #pragma unroll
            for (int j = 0; j < 4; j++) {
                o[i][j] *= factor;
                Ps[(ty * 4 + i) * 64 + tx * 4 + j] = s[i][j];
            }
        }
        __syncthreads();

        // PV accumulate
        #pragma unroll 4
        for (int kk = 0; kk < 64; kk++) {
            float4 v4 = *(const float4*)&Vs[kk * 64 + tx * 4];
            float vv[4] = {v4.x, v4.y, v4.z, v4.w};
            #pragma unroll
            for (int i = 0; i < 4; i++) {
                float a = Ps[(ty * 4 + i) * 64 + kk];
                #pragma unroll
                for (int j = 0; j < 4; j++)
                    o[i][j] = fmaf(a, vv[j], o[i][j]);
            }
        }
    }

    // Normalize + write to [B,S,E]
    #pragma unroll
    for (int i = 0; i < 4; i++) {
        float inv = 1.0f / l_i[i];
        int srow = q0 + ty * 4 + i;
        #pragma unroll
        for (int j = 0; j < 4; j++)
            g_ao[((size_t)b * Ss + srow) * Ee + h * 64 + tx * 4 + j] = o[i][j] * inv;
    }
}

// ---------------------------------------------------------------------------
// Output projection + residual: out = AO @ Wo^T + bo + q
// ---------------------------------------------------------------------------
__global__ __launch_bounds__(256) void oproj_kernel(
    const float* __restrict__ qin, const float* __restrict__ Wo,
    const float* __restrict__ bo, float* __restrict__ out)
{
    __shared__ float As[16][64];
    __shared__ float Bs[16][64];

    const int m0 = blockIdx.y * 64, n0 = blockIdx.x * 64;
    const int tid = threadIdx.x;
    const int ty = tid >> 4, tx = tid & 15;
    const int lm = tid >> 2, lk = (tid & 3) * 4;

    float acc[4][4] = {};

    for (int k0 = 0; k0 < Ee; k0 += 16) {
        float4 av = *(const float4*)(g_ao + (size_t)(m0 + lm) * Ee + k0 + lk);
        float4 wv = *(const float4*)(Wo + (size_t)(n0 + lm) * Ee + k0 + lk);
        As[lk + 0][lm] = av.x; As[lk + 1][lm] = av.y;
        As[lk + 2][lm] = av.z; As[lk + 3][lm] = av.w;
        Bs[lk + 0][lm] = wv.x; Bs[lk + 1][lm] = wv.y;
        Bs[lk + 2][lm] = wv.z; Bs[lk + 3][lm] = wv.w;
        __syncthreads();
        #pragma unroll
        for (int kk = 0; kk < 16; kk++) {
            float4 a4 = *(const float4*)&As[kk][ty * 4];
            float4 b4 = *(const float4*)&Bs[kk][tx * 4];
            float aa[4] = {a4.x, a4.y, a4.z, a4.w};
            float bb[4] = {b4.x, b4.y, b4.z, b4.w};
            #pragma unroll
            for (int i = 0; i < 4; i++)
                #pragma unroll
                for (int j = 0; j < 4; j++)
                    acc[i][j] = fmaf(aa[i], bb[j], acc[i][j]);
        }
        __syncthreads();
    }

    #pragma unroll
    for (int i = 0; i < 4; i++) {
        int m = m0 + ty * 4 + i;
        #pragma unroll
        for (int j = 0; j < 4; j++) {
            int n = n0 + tx * 4 + j;
            out[(size_t)m * Ee + n] = acc[i][j] + bo[n] + qin[(size_t)m * Ee + n];
        }
    }
}

extern "C" void kernel_launch(void* const* d_in, const int* in_sizes, int n_in,
                              void* d_out, int out_size)
{
    const float* q  = (const float*)d_in[0];
    const float* k  = (const float*)d_in[1];
    const float* v  = (const float*)d_in[2];
    const unsigned char* mask = (const unsigned char*)d_in[3];
    const float* Wq = (const float*)d_in[4];
    const float* bq = (const float*)d_in[5];
    const float* Wk = (const float*)d_in[6];
    const float* bk = (const float*)d_in[7];
    const float* Wv = (const float*)d_in[8];
    const float* bv = (const float*)d_in[9];
    const float* Wo = (const float*)d_in[10];
    const float* bo = (const float*)d_in[11];
    float* out = (float*)d_out;

    // QKV projections (fused, grid.z selects q/k/v)
    dim3 g1(Ee / 64, Mrows / 64, 3);
    qkv_kernel<<<g1, 256>>>(q, k, v, Wq, bq, Wk, bk, Wv, bv);

    // Attention: 64KB dynamic smem (opt-in; host-side attr, capture-safe)
    cudaFuncSetAttribute(attn_kernel, cudaFuncAttributeMaxDynamicSharedMemorySize, 65536);
    dim3 g2(Ss / 64, Bb * Hh);
    attn_kernel<<<g2, 256, 65536>>>(mask);

    // Output projection + residual
    dim3 g3(Ee / 64, Mrows / 64);
    oproj_kernel<<<g3, 256>>>(q, Wo, bo, out);
}

// round 2
// speedup vs baseline: 1.0014x; 1.0014x over previous
#include <cuda_runtime.h>

#define Bb 2
#define Ss 2048
#define Ee 1024
#define Hh 16
#define Dd 64
#define Mrows (Bb*Ss)

// Scratch (allocation-free rule: device globals)
__device__ float g_qh[Bb*Hh*Ss*Dd];   // [B,H,S,D]
__device__ float g_kh[Bb*Hh*Ss*Dd];
__device__ float g_vh[Bb*Hh*Ss*Dd];
__device__ float g_ao[Bb*Ss*Ee];      // attention out, [B,S,E]

// ---------------------------------------------------------------------------
// Fused QKV projection: out(m,n) = sum_k A[m,k] * W[n,k] + bias[n]
// Tiled 64x64x16, 256 threads, 4x4 microtile. Epilogue scatters to head layout.
// ---------------------------------------------------------------------------
__global__ __launch_bounds__(256) void qkv_kernel(
    const float* __restrict__ qin, const float* __restrict__ kin,
    const float* __restrict__ vin,
    const float* __restrict__ Wq, const float* __restrict__ bq,
    const float* __restrict__ Wk, const float* __restrict__ bk,
    const float* __restrict__ Wv, const float* __restrict__ bv)
{
    const float* A; const float* W; const float* bias; float* dst;
    if (blockIdx.z == 0)      { A = qin; W = Wq; bias = bq; dst = g_qh; }
    else if (blockIdx.z == 1) { A = kin; W = Wk; bias = bk; dst = g_kh; }
    else                      { A = vin; W = Wv; bias = bv; dst = g_vh; }

    __shared__ float As[16][64];
    __shared__ float Bs[16][64];

    const int m0 = blockIdx.y * 64, n0 = blockIdx.x * 64;
    const int tid = threadIdx.x;
    const int ty = tid >> 4, tx = tid & 15;
    const int lm = tid >> 2, lk = (tid & 3) * 4;

    float acc[4][4] = {};

    for (int k0 = 0; k0 < Ee; k0 += 16) {
        float4 av = *(const float4*)(A + (size_t)(m0 + lm) * Ee + k0 + lk);
        float4 wv = *(const float4*)(W + (size_t)(n0 + lm) * Ee + k0 + lk);
        As[lk + 0][lm] = av.x; As[lk + 1][lm] = av.y;
        As[lk + 2][lm] = av.z; As[lk + 3][lm] = av.w;
        Bs[lk + 0][lm] = wv.x; Bs[lk + 1][lm] = wv.y;
        Bs[lk + 2][lm] = wv.z; Bs[lk + 3][lm] = wv.w;
        __syncthreads();
        #pragma unroll
        for (int kk = 0; kk < 16; kk++) {
            float4 a4 = *(const float4*)&As[kk][ty * 4];
            float4 b4 = *(const float4*)&Bs[kk][tx * 4];
            float aa[4] = {a4.x, a4.y, a4.z, a4.w};
            float bb[4] = {b4.x, b4.y, b4.z, b4.w};
            #pragma unroll
            for (int i = 0; i < 4; i++)
                #pragma unroll
                for (int j = 0; j < 4; j++)
                    acc[i][j] = fmaf(aa[i], bb[j], acc[i][j]);
        }
        __syncthreads();
    }

    #pragma unroll
    for (int i = 0; i < 4; i++) {
        int m = m0 + ty * 4 + i;
        int b = m / Ss, s = m % Ss;
        #pragma unroll
        for (int j = 0; j < 4; j++) {
            int n = n0 + tx * 4 + j;
            int h = n >> 6, d = n & 63;
            dst[(((size_t)(b * Hh + h)) * Ss + s) * Dd + d] = acc[i][j] + bias[n];
        }
    }
}

// ---------------------------------------------------------------------------
// Flash attention fp32. One block = one (b,h) x 64-query tile, 256 threads.
// Dynamic smem (64KB): Qs [d][q], Ks [d][k], Vs [k][d], Ps [q][k].
// ---------------------------------------------------------------------------
__global__ __launch_bounds__(256) void attn_kernel(const unsigned char* __restrict__ mask)
{
    extern __shared__ float sm[];
    float* Qs = sm;            // 4096: Qs[d*64+q]
    float* Ks = sm + 4096;     // Ks[d*64+k]
    float* Vs = sm + 8192;     // Vs[k*64+d]
    float* Ps = sm + 12288;    // Ps[q*64+k]
    __shared__ float maskS[64];

    const int bh = blockIdx.y;
    const int b = bh >> 4, h = bh & 15;
    const int q0 = blockIdx.x * 64;
    const int tid = threadIdx.x;
    const int ty = tid >> 4, tx = tid & 15;

    const float* Qg = g_qh + ((size_t)(b * Hh + h) * Ss + q0) * Dd;
    // Load Q tile transposed (d-major)
    #pragma unroll
    for (int it = 0; it < 4; it++) {
        int v = tid + it * 256;          // float4 index, 1024 total
        int row = v >> 4, d0 = (v & 15) * 4;
        float4 x = *(const float4*)(Qg + row * 64 + d0);
        Qs[(d0 + 0) * 64 + row] = x.x; Qs[(d0 + 1) * 64 + row] = x.y;
        Qs[(d0 + 2) * 64 + row] = x.z; Qs[(d0 + 3) * 64 + row] = x.w;
    }

    float m_i[4], l_i[4], o[4][4];
    #pragma unroll
    for (int i = 0; i < 4; i++) {
        m_i[i] = -1e30f; l_i[i] = 0.f;
        #pragma unroll
        for (int j = 0; j < 4; j++) o[i][j] = 0.f;
    }

    const float* Kg0 = g_kh + (size_t)(b * Hh + h) * Ss * Dd;
    const float* Vg0 = g_vh + (size_t)(b * Hh + h) * Ss * Dd;

    for (int t = 0; t < Ss / 64; t++) {
        __syncthreads();   // previous PV done with Vs/Ps
        const float* Kg = Kg0 + t * 64 * 64;
        const float* Vg = Vg0 + t * 64 * 64;
        #pragma unroll
        for (int it = 0; it < 4; it++) {
            int v = tid + it * 256;
            int row = v >> 4, d0 = (v & 15) * 4;
            float4 x = *(const float4*)(Kg + row * 64 + d0);
            Ks[(d0 + 0) * 64 + row] = x.x; Ks[(d0 + 1) * 64 + row] = x.y;
            Ks[(d0 + 2) * 64 + row] = x.z; Ks[(d0 + 3) * 64 + row] = x.w;
            *(float4*)(Vs + v * 4) = *(const float4*)(Vg + v * 4);
        }
        if (tid < 64)
            maskS[tid] = mask[b * Ss + t * 64 + tid] ? -1e30f : 0.0f;
        __syncthreads();

        // Scores: s = 0.125 * Q K^T + mask
        float s[4][4];
        #pragma unroll
        for (int i = 0; i < 4; i++)
            #pragma unroll
            for (int j = 0; j < 4; j++) s[i][j] = 0.f;

        #pragma unroll 8
        for (int d = 0; d < 64; d++) {
            float4 a4 = *(const float4*)&Qs[d * 64 + ty * 4];
            float4 b4 = *(const float4*)&Ks[d * 64 + tx * 4];
            float aa[4] = {a4.x, a4.y, a4.z, a4.w};
            float bb[4] = {b4.x, b4.y, b4.z, b4.w};
            #pragma unroll
            for (int i = 0; i < 4; i++)
                #pragma unroll
                for (int j = 0; j < 4; j++)
                    s[i][j] = fmaf(aa[i], bb[j], s[i][j]);
        }
        #pragma unroll
        for (int i = 0; i < 4; i++)
            #pragma unroll
            for (int j = 0; j < 4; j++)
                s[i][j] = s[i][j] * 0.125f + maskS[tx * 4 + j];

        // Online softmax; row groups = 16 lanes (same ty within warp)
        #pragma unroll
        for (int i = 0; i < 4; i++) {
            float tm = fmaxf(fmaxf(s[i][0], s[i][1]), fmaxf(s[i][2], s[i][3]));
            #pragma unroll
            for (int off = 1; off < 16; off <<= 1)
                tm = fmaxf(tm, __shfl_xor_sync(0xffffffffu, tm, off, 16));
            float mn = fmaxf(m_i[i], tm);
            float factor = __expf(m_i[i] - mn);
            float rs = 0.f;
            #pragma unroll
            for (int j = 0; j < 4; j++) {
                float p = __expf(s[i][j] - mn);
                s[i][j] = p;
                rs += p;
            }
            #pragma unroll
            for (int off = 1; off < 16; off <<= 1)
                rs += __shfl_xor_sync(0xffffffffu, rs, off, 16);
            l_i[i] = l_i[i] * factor + rs;
            m_i[i] = mn;
            #pragma unroll
            for (int j = 0; j < 4; j++) {
                o[i][j] *= factor;
                Ps[(ty * 4 + i) * 64 + tx * 4 + j] = s[i][j];
            }
        }
        __syncthreads();

        // PV accumulate
        #pragma unroll 4
        for (int kk = 0; kk < 64; kk++) {
            float4 v4 = *(const float4*)&Vs[kk * 64 + tx * 4];
            float vv[4] = {v4.x, v4.y, v4.z, v4.w};
            #pragma unroll
            for (int i = 0; i < 4; i++) {
                float a = Ps[(ty * 4 + i) * 64 + kk];
                #pragma unroll
                for (int j = 0; j < 4; j++)
                    o[i][j] = fmaf(a, vv[j], o[i][j]);
            }
        }
    }

    // Normalize + write to [B,S,E]
    #pragma unroll
    for (int i = 0; i < 4; i++) {
        float inv = 1.0f / l_i[i];
        int srow = q0 + ty * 4 + i;
        #pragma unroll
        for (int j = 0; j < 4; j++)
            g_ao[((size_t)b * Ss + srow) * Ee + h * 64 + tx * 4 + j] = o[i][j] * inv;
    }
}

// ---------------------------------------------------------------------------
// Output projection + residual: out = AO @ Wo^T + bo + q
// ---------------------------------------------------------------------------
__global__ __launch_bounds__(256) void oproj_kernel(
    const float* __restrict__ qin, const float* __restrict__ Wo,
    const float* __restrict__ bo, float* __restrict__ out)
{
    __shared__ float As[16][64];
    __shared__ float Bs[16][64];

    const int m0 = blockIdx.y * 64, n0 = blockIdx.x * 64;
    const int tid = threadIdx.x;
    const int ty = tid >> 4, tx = tid & 15;
    const int lm = tid >> 2, lk = (tid & 3) * 4;

    float acc[4][4] = {};

    for (int k0 = 0; k0 < Ee; k0 += 16) {
        float4 av = *(const float4*)(g_ao + (size_t)(m0 + lm) * Ee + k0 + lk);
        float4 wv = *(const float4*)(Wo + (size_t)(n0 + lm) * Ee + k0 + lk);
        As[lk + 0][lm] = av.x; As[lk + 1][lm] = av.y;
        As[lk + 2][lm] = av.z; As[lk + 3][lm] = av.w;
        Bs[lk + 0][lm] = wv.x; Bs[lk + 1][lm] = wv.y;
        Bs[lk + 2][lm] = wv.z; Bs[lk + 3][lm] = wv.w;
        __syncthreads();
        #pragma unroll
        for (int kk = 0; kk < 16; kk++) {
            float4 a4 = *(const float4*)&As[kk][ty * 4];
            float4 b4 = *(const float4*)&Bs[kk][tx * 4];
            float aa[4] = {a4.x, a4.y, a4.z, a4.w};
            float bb[4] = {b4.x, b4.y, b4.z, b4.w};
            #pragma unroll
            for (int i = 0; i < 4; i++)
                #pragma unroll
                for (int j = 0; j < 4; j++)
                    acc[i][j] = fmaf(aa[i], bb[j], acc[i][j]);
        }
        __syncthreads();
    }

    #pragma unroll
    for (int i = 0; i < 4; i++) {
        int m = m0 + ty * 4 + i;
        #pragma unroll
        for (int j = 0; j < 4; j++) {
            int n = n0 + tx * 4 + j;
            out[(size_t)m * Ee + n] = acc[i][j] + bo[n] + qin[(size_t)m * Ee + n];
        }
    }
}

extern "C" void kernel_launch(void* const* d_in, const int* in_sizes, int n_in,
                              void* d_out, int out_size)
{
    const float* q  = (const float*)d_in[0];
    const float* k  = (const float*)d_in[1];
    const float* v  = (const float*)d_in[2];
    const unsigned char* mask = (const unsigned char*)d_in[3];
    const float* Wq = (const float*)d_in[4];
    const float* bq = (const float*)d_in[5];
    const float* Wk = (const float*)d_in[6];
    const float* bk = (const float*)d_in[7];
    const float* Wv = (const float*)d_in[8];
    const float* bv = (const float*)d_in[9];
    const float* Wo = (const float*)d_in[10];
    const float* bo = (const float*)d_in[11];
    float* out = (float*)d_out;

    // QKV projections (fused, grid.z selects q/k/v)
    dim3 g1(Ee / 64, Mrows / 64, 3);
    qkv_kernel<<<g1, 256>>>(q, k, v, Wq, bq, Wk, bk, Wv, bv);

    // Attention: 64KB dynamic smem (opt-in; host-side attr, capture-safe)
    cudaFuncSetAttribute(attn_kernel, cudaFuncAttributeMaxDynamicSharedMemorySize, 65536);
    dim3 g2(Ss / 64, Bb * Hh);
    attn_kernel<<<g2, 256, 65536>>>(mask);

    // Output projection + residual
    dim3 g3(Ee / 64, Mrows / 64);
    oproj_kernel<<<g3, 256>>>(q, Wo, bo, out);
}

// round 4
// speedup vs baseline: 1.8189x; 1.8164x over previous
#include <cuda_runtime.h>
#include <cuda_bf16.h>

#define Bb 2
#define Ss 2048
#define Ee 1024
#define Hh 16
#define Dd 64
#define Mrows (Bb*Ss)

// Scratch (allocation-free rule: device globals)
__device__ float g_qh[(size_t)Bb*Hh*Ss*Dd];   // [B,H,S,D]
__device__ float g_kh[(size_t)Bb*Hh*Ss*Dd];   // [B,H,S,D]
__device__ float g_vt[(size_t)Bb*Hh*Dd*Ss];   // [B,H,D,S]  (V transposed)
__device__ float g_ao[(size_t)Bb*Ss*Ee];      // [B,S,E]

// ---------------- helpers ----------------
__device__ __forceinline__ unsigned packbf(float e0, float e1){
    unsigned r;   // lo half = e0, hi half = e1
    asm("cvt.rn.bf16x2.f32 %0, %1, %2;" : "=r"(r) : "f"(e1), "f"(e0));
    return r;
}
__device__ __forceinline__ float bferr(float x){
    __nv_bfloat16 h = __float2bfloat16(x);
    return x - __bfloat162float(h);
}
// D += A(16x16 bf16, row) * B(16x8 bf16, col)
__device__ __forceinline__ void mma16816(float* d, const unsigned* a, const unsigned* b){
    asm volatile(
        "mma.sync.aligned.m16n8k16.row.col.f32.bf16.bf16.f32 "
        "{%0,%1,%2,%3}, {%4,%5,%6,%7}, {%8,%9}, {%0,%1,%2,%3};"
        : "+f"(d[0]), "+f"(d[1]), "+f"(d[2]), "+f"(d[3])
        : "r"(a[0]), "r"(a[1]), "r"(a[2]), "r"(a[3]), "r"(b[0]), "r"(b[1]));
}

// ===========================================================================
// GEMM core: C[m,n] = sum_k A[m,k] * B[n,k]   (both row-major, K-contig)
// CTA 128x128, BK=32, 256 threads, 8 warps (4m x 2n), warp tile 32x64.
// smem: hi/lo bf16 tiles, u32-packed, row stride 17 u32 (34 bf16).
// ===========================================================================
struct GemmSmem {
    unsigned Ah[128*17], Al[128*17], Bh[128*17], Bl[128*17];
};

__device__ __forceinline__ void gemm_stage_load(GemmSmem& S, const float* __restrict__ A,
                                                const float* __restrict__ B,
                                                int m0, int n0, int k0, int tid)
{
    const int r = tid >> 1;
    const int cb = (tid & 1) * 16;
    const float* Ar = A + (size_t)(m0 + r) * Ee + k0 + cb;
    const float* Br = B + (size_t)(n0 + r) * Ee + k0 + cb;
    #pragma unroll
    for (int i = 0; i < 4; i++) {
        float4 x = *(const float4*)(Ar + i*4);
        float4 y = *(const float4*)(Br + i*4);
        int ci = (cb + i*4) >> 1;
        S.Ah[r*17 + ci]     = packbf(x.x, x.y);
        S.Ah[r*17 + ci + 1] = packbf(x.z, x.w);
        S.Al[r*17 + ci]     = packbf(bferr(x.x), bferr(x.y));
        S.Al[r*17 + ci + 1] = packbf(bferr(x.z), bferr(x.w));
        S.Bh[r*17 + ci]     = packbf(y.x, y.y);
        S.Bh[r*17 + ci + 1] = packbf(y.z, y.w);
        S.Bl[r*17 + ci]     = packbf(bferr(y.x), bferr(y.y));
        S.Bl[r*17 + ci + 1] = packbf(bferr(y.z), bferr(y.w));
    }
}

__device__ __forceinline__ void gemm_mainloop(GemmSmem& S, float acc[2][8][4],
                                              const float* __restrict__ A,
                                              const float* __restrict__ B,
                                              int m0, int n0, int tid)
{
    const int lane = tid & 31, wid = tid >> 5;
    const int g = lane >> 2, t = lane & 3;
    const int wm = (wid & 3) * 32, wn = (wid >> 2) * 64;

    for (int k0 = 0; k0 < Ee; k0 += 32) {
        gemm_stage_load(S, A, B, m0, n0, k0, tid);
        __syncthreads();
        #pragma unroll
        for (int kk = 0; kk < 2; kk++) {
            const int ko = kk * 8;
            unsigned ah[2][4], al[2][4];
            #pragma unroll
            for (int mt = 0; mt < 2; mt++) {
                int r0 = wm + mt*16 + g;
                ah[mt][0] = S.Ah[r0*17 + ko + t];
                ah[mt][1] = S.Ah[(r0+8)*17 + ko + t];
                ah[mt][2] = S.Ah[r0*17 + ko + 4 + t];
                ah[mt][3] = S.Ah[(r0+8)*17 + ko + 4 + t];
                al[mt][0] = S.Al[r0*17 + ko + t];
                al[mt][1] = S.Al[(r0+8)*17 + ko + t];
                al[mt][2] = S.Al[r0*17 + ko + 4 + t];
                al[mt][3] = S.Al[(r0+8)*17 + ko + 4 + t];
            }
            #pragma unroll
            for (int nt = 0; nt < 8; nt++) {
                int n = wn + nt*8 + g;
                unsigned bh[2] = {S.Bh[n*17 + ko + t], S.Bh[n*17 + ko + 4 + t]};
                unsigned bl[2] = {S.Bl[n*17 + ko + t], S.Bl[n*17 + ko + 4 + t]};
                #pragma unroll
                for (int mt = 0; mt < 2; mt++) {
                    mma16816(acc[mt][nt], ah[mt], bh);
                    mma16816(acc[mt][nt], ah[mt], bl);
                    mma16816(acc[mt][nt], al[mt], bh);
                }
            }
        }
        __syncthreads();
    }
}

// ===========================================================================
// QKV projection (grid.z selects q/k/v); V written transposed to g_vt.
// ===========================================================================
__global__ __launch_bounds__(256) void qkv_mma(
    const float* __restrict__ qin, const float* __restrict__ kin,
    const float* __restrict__ vin,
    const float* __restrict__ Wq, const float* __restrict__ bq,
    const float* __restrict__ Wk, const float* __restrict__ bk,
    const float* __restrict__ Wv, const float* __restrict__ bv)
{
    __shared__ GemmSmem S;
    const int tid = threadIdx.x;
    const int z = blockIdx.z;
    const float *A, *W, *bias;
    if (z == 0)      { A = qin; W = Wq; bias = bq; }
    else if (z == 1) { A = kin; W = Wk; bias = bk; }
    else             { A = vin; W = Wv; bias = bv; }
    const int m0 = blockIdx.y * 128, n0 = blockIdx.x * 128;

    float acc[2][8][4] = {};
    gemm_mainloop(S, acc, A, W, m0, n0, tid);

    const int lane = tid & 31, wid = tid >> 5;
    const int g = lane >> 2, t = lane & 3;
    const int wm = (wid & 3) * 32, wn = (wid >> 2) * 64;

    #pragma unroll
    for (int mt = 0; mt < 2; mt++) {
        #pragma unroll
        for (int nt = 0; nt < 8; nt++) {
            int m = m0 + wm + mt*16 + g;
            int n = n0 + wn + nt*8 + t*2;
            float b0v = bias[n], b1v = bias[n+1];
            int b = m >> 11, s = m & 2047;
            int h = n >> 6, d = n & 63;
            float v00 = acc[mt][nt][0] + b0v, v01 = acc[mt][nt][1] + b1v;
            float v10 = acc[mt][nt][2] + b0v, v11 = acc[mt][nt][3] + b1v;
            if (z == 0) {
                float* p = g_qh + (((size_t)(b*Hh + h))*Ss + s)*Dd + d;
                p[0] = v00; p[1] = v01;
                p += 8 * Dd;               // s+8
                p[0] = v10; p[1] = v11;
            } else if (z == 1) {
                float* p = g_kh + (((size_t)(b*Hh + h))*Ss + s)*Dd + d;
                p[0] = v00; p[1] = v01;
                p += 8 * Dd;
                p[0] = v10; p[1] = v11;
            } else {
                float* p = g_vt + (((size_t)(b*Hh + h))*Dd + d)*Ss + s;
                p[0] = v00; p[Ss] = v01;
                p[8] = v10; p[Ss + 8] = v11;
            }
        }
    }
}

// ===========================================================================
// Output projection + bias + residual
// ===========================================================================
__global__ __launch_bounds__(256) void oproj_mma(
    const float* __restrict__ qin, const float* __restrict__ Wo,
    const float* __restrict__ bo, float* __restrict__ out)
{
    __shared__ GemmSmem S;
    const int tid = threadIdx.x;
    const int m0 = blockIdx.y * 128, n0 = blockIdx.x * 128;

    float acc[2][8][4] = {};
    gemm_mainloop(S, acc, g_ao, Wo, m0, n0, tid);

    const int lane = tid & 31, wid = tid >> 5;
    const int g = lane >> 2, t = lane & 3;
    const int wm = (wid & 3) * 32, wn = (wid >> 2) * 64;

    #pragma unroll
    for (int mt = 0; mt < 2; mt++) {
        #pragma unroll
        for (int nt = 0; nt < 8; nt++) {
            int m = m0 + wm + mt*16 + g;
            int n = n0 + wn + nt*8 + t*2;
            float b0v = bo[n], b1v = bo[n+1];
            size_t i0 = (size_t)m * Ee + n;
            size_t i1 = (size_t)(m+8) * Ee + n;
            out[i0]   = acc[mt][nt][0] + b0v + qin[i0];
            out[i0+1] = acc[mt][nt][1] + b1v + qin[i0+1];
            out[i1]   = acc[mt][nt][2] + b0v + qin[i1];
            out[i1+1] = acc[mt][nt][3] + b1v + qin[i1+1];
        }
    }
}

// ===========================================================================
// Flash attention, mma.sync bf16x3, no-max softmax.
// CTA: one (b,h) x 128 queries, 256 threads (8 warps, warp = 16 q rows).
// K tile 64 keys. P fragments built in-register from QK accumulators.
// ===========================================================================
__global__ __launch_bounds__(256) void attn_mma(const unsigned char* __restrict__ mask)
{
    __shared__ unsigned Kh[64*33], Kl[64*33], Vh[64*33], Vl[64*33];
    __shared__ float maskS[64];

    const int tid = threadIdx.x;
    const int lane = tid & 31, w = tid >> 5;
    const int g = lane >> 2, t = lane & 3;
    const int bh = blockIdx.y, b = bh >> 4, h = bh & 15;
    const int q0 = blockIdx.x * 128;

    // ---- stage Q (128x64) into the K/V buffers, grab fragments, release ----
    {
        const float* Qg = g_qh + ((size_t)bh * Ss + q0) * Dd;
        const int r = tid >> 1;
        const int cb = (tid & 1) * 32;
        unsigned* H = (r < 64) ? Kh : Vh;
        unsigned* L = (r < 64) ? Kl : Vl;
        const int rr = r & 63;
        #pragma unroll
        for (int i = 0; i < 8; i++) {
            float4 x = *(const float4*)(Qg + (size_t)r*64 + cb + i*4);
            int ci = (cb + i*4) >> 1;
            H[rr*33 + ci]     = packbf(x.x, x.y);
            H[rr*33 + ci + 1] = packbf(x.z, x.w);
            L[rr*33 + ci]     = packbf(bferr(x.x), bferr(x.y));
            L[rr*33 + ci + 1] = packbf(bferr(x.z), bferr(x.w));
        }
    }
    __syncthreads();

    unsigned qh[4][4], ql[4][4];
    {
        const int r0 = w*16 + g;
        const unsigned* H = (w < 4) ? Kh : Vh;
        const unsigned* L = (w < 4) ? Kl : Vl;
        const int rr = r0 & 63;
        #pragma unroll
        for (int dt = 0; dt < 4; dt++) {
            int ko = dt*8;
            qh[dt][0] = H[rr*33 + ko + t];
            qh[dt][1] = H[(rr+8)*33 + ko + t];
            qh[dt][2] = H[rr*33 + ko + 4 + t];
            qh[dt][3] = H[(rr+8)*33 + ko + 4 + t];
            ql[dt][0] = L[rr*33 + ko + t];
            ql[dt][1] = L[(rr+8)*33 + ko + t];
            ql[dt][2] = L[rr*33 + ko + 4 + t];
            ql[dt][3] = L[(rr+8)*33 + ko + 4 + t];
        }
    }
    __syncthreads();

    float O[8][4] = {};
    float l0 = 0.f, l1 = 0.f;

    const float* Kg0 = g_kh + (size_t)bh * Ss * Dd;
    const float* Vg0 = g_vt + (size_t)bh * Dd * Ss;
    const unsigned char* mp = mask + (size_t)b * Ss;

    for (int kt = 0; kt < Ss/64; kt++) {
        // load K tile [64 keys][64 d] and V tile [64 d][64 keys]
        {
            const int r = tid >> 2;
            const int cb = (tid & 3) * 16;
            const float* Kr = Kg0 + (size_t)(kt*64 + r) * Dd + cb;
            const float* Vr = Vg0 + (size_t)r * Ss + kt*64 + cb;
            #pragma unroll
            for (int i = 0; i < 4; i++) {
                float4 x = *(const float4*)(Kr + i*4);
                float4 y = *(const float4*)(Vr + i*4);
                int ci = (cb + i*4) >> 1;
                Kh[r*33 + ci]     = packbf(x.x, x.y);
                Kh[r*33 + ci + 1] = packbf(x.z, x.w);
                Kl[r*33 + ci]     = packbf(bferr(x.x), bferr(x.y));
                Kl[r*33 + ci + 1] = packbf(bferr(x.z), bferr(x.w));
                Vh[r*33 + ci]     = packbf(y.x, y.y);
                Vh[r*33 + ci + 1] = packbf(y.z, y.w);
                Vl[r*33 + ci]     = packbf(bferr(y.x), bferr(y.y));
                Vl[r*33 + ci + 1] = packbf(bferr(y.z), bferr(y.w));
            }
            if (tid < 64) maskS[tid] = mp[kt*64 + tid] ? -1e9f : 0.f;
        }
        __syncthreads();

        // scores S = Q K^T (bf16x3)
        float Sc[8][4] = {};
        #pragma unroll
        for (int dt = 0; dt < 4; dt++) {
            const int ko = dt*8;
            #pragma unroll
            for (int nt = 0; nt < 8; nt++) {
                int n = nt*8 + g;
                unsigned kbh[2] = {Kh[n*33 + ko + t], Kh[n*33 + ko + 4 + t]};
                unsigned kbl[2] = {Kl[n*33 + ko + t], Kl[n*33 + ko + 4 + t]};
                mma16816(Sc[nt], qh[dt], kbh);
                mma16816(Sc[nt], qh[dt], kbl);
                mma16816(Sc[nt], ql[dt], kbh);
            }
        }

        // softmax (no max subtraction) + pack P fragments in-register
        unsigned pah[4][4], pal[4][4];
        #pragma unroll
        for (int nt = 0; nt < 8; nt++) {
            int j = nt*8 + t*2;
            float mv0 = maskS[j], mv1 = maskS[j+1];
            float p0 = __expf(Sc[nt][0]*0.125f + mv0);
            float p1 = __expf(Sc[nt][1]*0.125f + mv1);
            float p2 = __expf(Sc[nt][2]*0.125f + mv0);
            float p3 = __expf(Sc[nt][3]*0.125f + mv1);
            l0 += p0 + p1;
            l1 += p2 + p3;
            int kk = nt >> 1, hi = (nt & 1) * 2;
            pah[kk][hi]   = packbf(p0, p1);
            pah[kk][hi+1] = packbf(p2, p3);
            pal[kk][hi]   = packbf(bferr(p0), bferr(p1));
            pal[kk][hi+1] = packbf(bferr(p2), bferr(p3));
        }

        // O += P V  (bf16x3: PhVh + PlVh + PhVl)
        #pragma unroll
        for (int kk = 0; kk < 4; kk++) {
            const int ko = kk*8;
            #pragma unroll
            for (int nt = 0; nt < 8; nt++) {
                int n = nt*8 + g;
                unsigned vbh[2] = {Vh[n*33 + ko + t], Vh[n*33 + ko + 4 + t]};
                unsigned vbl[2] = {Vl[n*33 + ko + t], Vl[n*33 + ko + 4 + t]};
                mma16816(O[nt], pah[kk], vbh);
                mma16816(O[nt], pal[kk], vbh);
                mma16816(O[nt], pah[kk], vbl);
            }
        }
        __syncthreads();
    }

    // reduce row sums across the 4 lanes sharing each row
    #pragma unroll
    for (int off = 1; off < 4; off <<= 1) {
        l0 += __shfl_xor_sync(0xffffffffu, l0, off);
        l1 += __shfl_xor_sync(0xffffffffu, l1, off);
    }
    const float inv0 = 1.0f / l0, inv1 = 1.0f / l1;

    const int q = q0 + w*16 + g;
    float* d0 = g_ao + ((size_t)b * Ss + q) * Ee + h*64;
    float* d1 = g_ao + ((size_t)b * Ss + q + 8) * Ee + h*64;
    #pragma unroll
    for (int nt = 0; nt < 8; nt++) {
        int c = nt*8 + t*2;
        d0[c]   = O[nt][0] * inv0;
        d0[c+1] = O[nt][1] * inv0;
        d1[c]   = O[nt][2] * inv1;
        d1[c+1] = O[nt][3] * inv1;
    }
}

// ===========================================================================
extern "C" void kernel_launch(void* const* d_in, const int* in_sizes, int n_in,
                              void* d_out, int out_size)
{
    const float* q  = (const float*)d_in[0];
    const float* k  = (const float*)d_in[1];
    const float* v  = (const float*)d_in[2];
    const unsigned char* mask = (const unsigned char*)d_in[3];
    const float* Wq = (const float*)d_in[4];
    const float* bq = (const float*)d_in[5];
    const float* Wk = (const float*)d_in[6];
    const float* bk = (const float*)d_in[7];
    const float* Wv = (const float*)d_in[8];
    const float* bv = (const float*)d_in[9];
    const float* Wo = (const float*)d_in[10];
    const float* bo = (const float*)d_in[11];
    float* out = (float*)d_out;

    dim3 g1(Ee/128, Mrows/128, 3);
    qkv_mma<<<g1, 256>>>(q, k, v, Wq, bq, Wk, bk, Wv, bv);

    dim3 g2(Ss/128, Bb*Hh);
    attn_mma<<<g2, 256>>>(mask);

    dim3 g3(Ee/128, Mrows/128);
    oproj_mma<<<g3, 256>>>(q, Wo, bo, out);
}

// round 5
// speedup vs baseline: 2.8571x; 1.5708x over previous
#include <cuda_runtime.h>
#include <cuda_bf16.h>

#define Bb 2
#define Ss 2048
#define Ee 1024
#define Hh 16
#define Dd 64
#define Mrows (Bb*Ss)

// Scratch (allocation-free rule: device globals)
__device__ float g_qh[(size_t)Bb*Hh*Ss*Dd];   // [B,H,S,D]
__device__ float g_kh[(size_t)Bb*Hh*Ss*Dd];   // [B,H,S,D]
__device__ float g_vt[(size_t)Bb*Hh*Dd*Ss];   // [B,H,D,S]  (V transposed)
__device__ float g_ao[(size_t)Bb*Ss*Ee];      // [B,S,E]

// ---------------- helpers ----------------
__device__ __forceinline__ unsigned smem_u32(const void* p){
    unsigned a;
    asm("{ .reg .u64 t; cvta.to.shared.u64 t, %1; cvt.u32.u64 %0, t; }"
        : "=r"(a) : "l"(p));
    return a;
}
__device__ __forceinline__ unsigned packbf(float e0, float e1){
    unsigned r;   // lo half = e0, hi half = e1
    asm("cvt.rn.bf16x2.f32 %0, %1, %2;" : "=r"(r) : "f"(e1), "f"(e0));
    return r;
}
__device__ __forceinline__ float bferr(float x){
    __nv_bfloat16 h = __float2bfloat16(x);
    return x - __bfloat162float(h);
}
__device__ __forceinline__ void mma16816(float* d, const unsigned* a, const unsigned* b){
    asm volatile(
        "mma.sync.aligned.m16n8k16.row.col.f32.bf16.bf16.f32 "
        "{%0,%1,%2,%3}, {%4,%5,%6,%7}, {%8,%9}, {%0,%1,%2,%3};"
        : "+f"(d[0]), "+f"(d[1]), "+f"(d[2]), "+f"(d[3])
        : "r"(a[0]), "r"(a[1]), "r"(a[2]), "r"(a[3]), "r"(b[0]), "r"(b[1]));
}
__device__ __forceinline__ void ldsm4(unsigned addr, unsigned* r){
    asm volatile("ldmatrix.sync.aligned.m8n8.x4.shared.b16 {%0,%1,%2,%3}, [%4];"
                 : "=r"(r[0]), "=r"(r[1]), "=r"(r[2]), "=r"(r[3]) : "r"(addr));
}
__device__ __forceinline__ void sts2(unsigned a, unsigned v0, unsigned v1){
    asm volatile("st.shared.v2.b32 [%0], {%1, %2};" :: "r"(a), "r"(v0), "r"(v1) : "memory");
}

// ===========================================================================
// GEMM core: C[m,n] = sum_k A[m,k]*B[n,k].  CTA 128x128, BK=32, 256 threads,
// 8 warps (4m x 2n), warp tile 32x64. Double-buffered hi/lo bf16 smem,
// row stride 20 u32 (16B-aligned, conflict-free ldmatrix). Reg prefetch.
// ===========================================================================
#define GARR 10240            // bytes per array (128 rows * 20 u32 * 4)
#define GSTG (4*GARR)         // per stage
#define GE_DYN (2*GSTG)       // 81920 B

__device__ __forceinline__ void gemm_tc(float acc[2][8][4],
        const float* __restrict__ A, const float* __restrict__ B,
        int m0, int n0, unsigned sbase, int tid)
{
    const int lane = tid & 31, wid = tid >> 5;
    const int wm = (wid & 3) * 32, wn = (wid >> 2) * 64;

    const int r = tid >> 1, cbf = (tid & 1) * 16;
    const float* Ar = A + (size_t)(m0 + r) * Ee + cbf;
    const float* Br = B + (size_t)(n0 + r) * Ee + cbf;

    float4 pa[4], pb[4];
    #pragma unroll
    for (int i = 0; i < 4; i++) {
        pa[i] = *(const float4*)(Ar + i*4);
        pb[i] = *(const float4*)(Br + i*4);
    }

    // ldmatrix per-lane byte offsets (add ko*4 at use)
    unsigned aoff[2];
    #pragma unroll
    for (int mt = 0; mt < 2; mt++) {
        int row = wm + mt*16 + ((lane>>3)&1)*8 + (lane&7);
        aoff[mt] = (unsigned)((row*20 + ((lane>>4)<<2)) * 4);
    }
    unsigned boff[4];
    #pragma unroll
    for (int np = 0; np < 4; np++) {
        int row = wn + np*16 + ((lane>>4)&1)*8 + (lane&7);
        boff[np] = (unsigned)((row*20 + (((lane>>3)&1)<<2)) * 4);
    }

    const unsigned rowb0 = (unsigned)((r*20 + (tid&1)*8) * 4);

    for (int s = 0; s < Ee/32; s++) {
        const unsigned sb = sbase + (unsigned)(s & 1) * GSTG;
        // STS current prefetch
        #pragma unroll
        for (int i = 0; i < 4; i++) {
            float4 x = pa[i], y = pb[i];
            unsigned off = sb + rowb0 + i*8;
            sts2(off + 0*GARR, packbf(x.x,x.y), packbf(x.z,x.w));
            sts2(off + 1*GARR, packbf(bferr(x.x),bferr(x.y)), packbf(bferr(x.z),bferr(x.w)));
            sts2(off + 2*GARR, packbf(y.x,y.y), packbf(y.z,y.w));
            sts2(off + 3*GARR, packbf(bferr(y.x),bferr(y.y)), packbf(bferr(y.z),bferr(y.w)));
        }
        __syncthreads();
        if (s + 1 < Ee/32) {
            #pragma unroll
            for (int i = 0; i < 4; i++) {
                pa[i] = *(const float4*)(Ar + (s+1)*32 + i*4);
                pb[i] = *(const float4*)(Br + (s+1)*32 + i*4);
            }
        }
        #pragma unroll
        for (int kk = 0; kk < 2; kk++) {
            const unsigned kob = kk * 32;
            unsigned ah[2][4], al[2][4];
            #pragma unroll
            for (int mt = 0; mt < 2; mt++) {
                ldsm4(sb + 0*GARR + aoff[mt] + kob, ah[mt]);
                ldsm4(sb + 1*GARR + aoff[mt] + kob, al[mt]);
            }
            #pragma unroll
            for (int np = 0; np < 4; np++) {
                unsigned bh[4], bl[4];
                ldsm4(sb + 2*GARR + boff[np] + kob, bh);
                ldsm4(sb + 3*GARR + boff[np] + kob, bl);
                #pragma unroll
                for (int hf = 0; hf < 2; hf++) {
                    const int nt = np*2 + hf;
                    #pragma unroll
                    for (int mt = 0; mt < 2; mt++) {
                        mma16816(acc[mt][nt], ah[mt], bh + hf*2);
                        mma16816(acc[mt][nt], ah[mt], bl + hf*2);
                        mma16816(acc[mt][nt], al[mt], bh + hf*2);
                    }
                }
            }
        }
        // single sync per stage: next STS targets the other buffer
    }
    __syncthreads();
}

// ===========================================================================
// QKV projection (grid.z selects q/k/v); V written transposed to g_vt.
// ===========================================================================
__global__ __launch_bounds__(256, 1) void qkv_mma(
    const float* __restrict__ qin, const float* __restrict__ kin,
    const float* __restrict__ vin,
    const float* __restrict__ Wq, const float* __restrict__ bq,
    const float* __restrict__ Wk, const float* __restrict__ bk,
    const float* __restrict__ Wv, const float* __restrict__ bv)
{
    extern __shared__ char smraw[];
    unsigned sbase = smem_u32(smraw);
    const int tid = threadIdx.x;
    const int z = blockIdx.z;
    const float *A, *W, *bias;
    if (z == 0)      { A = qin; W = Wq; bias = bq; }
    else if (z == 1) { A = kin; W = Wk; bias = bk; }
    else             { A = vin; W = Wv; bias = bv; }
    const int m0 = blockIdx.y * 128, n0 = blockIdx.x * 128;

    float acc[2][8][4] = {};
    gemm_tc(acc, A, W, m0, n0, sbase, tid);

    const int lane = tid & 31, wid = tid >> 5;
    const int g = lane >> 2, t = lane & 3;
    const int wm = (wid & 3) * 32, wn = (wid >> 2) * 64;

    #pragma unroll
    for (int mt = 0; mt < 2; mt++) {
        #pragma unroll
        for (int nt = 0; nt < 8; nt++) {
            int m = m0 + wm + mt*16 + g;
            int n = n0 + wn + nt*8 + t*2;
            float b0v = bias[n], b1v = bias[n+1];
            int b = m >> 11, s = m & 2047;
            int h = n >> 6, d = n & 63;
            float v00 = acc[mt][nt][0] + b0v, v01 = acc[mt][nt][1] + b1v;
            float v10 = acc[mt][nt][2] + b0v, v11 = acc[mt][nt][3] + b1v;
            if (z == 0) {
                float* p = g_qh + (((size_t)(b*Hh + h))*Ss + s)*Dd + d;
                p[0] = v00; p[1] = v01;
                p += 8 * Dd;
                p[0] = v10; p[1] = v11;
            } else if (z == 1) {
                float* p = g_kh + (((size_t)(b*Hh + h))*Ss + s)*Dd + d;
                p[0] = v00; p[1] = v01;
                p += 8 * Dd;
                p[0] = v10; p[1] = v11;
            } else {
                float* p = g_vt + (((size_t)(b*Hh + h))*Dd + d)*Ss + s;
                p[0] = v00; p[Ss] = v01;
                p[8] = v10; p[Ss + 8] = v11;
            }
        }
    }
}

// ===========================================================================
// Output projection + bias + residual
// ===========================================================================
__global__ __launch_bounds__(256, 1) void oproj_mma(
    const float* __restrict__ qin, const float* __restrict__ Wo,
    const float* __restrict__ bo, float* __restrict__ out)
{
    extern __shared__ char smraw[];
    unsigned sbase = smem_u32(smraw);
    const int tid = threadIdx.x;
    const int m0 = blockIdx.y * 128, n0 = blockIdx.x * 128;

    float acc[2][8][4] = {};
    gemm_tc(acc, g_ao, Wo, m0, n0, sbase, tid);

    const int lane = tid & 31, wid = tid >> 5;
    const int g = lane >> 2, t = lane & 3;
    const int wm = (wid & 3) * 32, wn = (wid >> 2) * 64;

    #pragma unroll
    for (int mt = 0; mt < 2; mt++) {
        #pragma unroll
        for (int nt = 0; nt < 8; nt++) {
            int m = m0 + wm + mt*16 + g;
            int n = n0 + wn + nt*8 + t*2;
            float b0v = bo[n], b1v = bo[n+1];
            size_t i0 = (size_t)m * Ee + n;
            size_t i1 = (size_t)(m+8) * Ee + n;
            out[i0]   = acc[mt][nt][0] + b0v + qin[i0];
            out[i0+1] = acc[mt][nt][1] + b1v + qin[i0+1];
            out[i1]   = acc[mt][nt][2] + b0v + qin[i1];
            out[i1+1] = acc[mt][nt][3] + b1v + qin[i1+1];
        }
    }
}

// ===========================================================================
// Flash attention: ldmatrix + double buffer + reg prefetch, no-max softmax.
// CTA: one (b,h) x 128 queries, 256 threads. K tile 64. Q pre-scaled by
// 0.125*log2(e) so softmax is a single exp2f.
// Smem per stage: Kh,Kl,Vh,Vl [64 rows x 36 u32] + mask[64].
// ===========================================================================
#define AARR 9216              // 64*36*4
#define ASTG (4*AARR)          // 36864
#define AMSK (2*ASTG)          // 73728
#define AT_DYN (AMSK + 512)

__global__ __launch_bounds__(256, 1) void attn_mma(const unsigned char* __restrict__ mask)
{
    extern __shared__ char smraw[];
    unsigned sbase = smem_u32(smraw);
    const int tid = threadIdx.x;
    const int lane = tid & 31, w = tid >> 5;
    const int g = lane >> 2, t = lane & 3;
    const int bh = blockIdx.y, b = bh >> 4, h = bh & 15;
    const int q0 = blockIdx.x * 128;

    const float QSCALE = 0.125f * 1.4426950408889634f;  // fold 1/8 and log2(e)

    // ---- stage Q (128x64, scaled) into stage-0 buffers ----
    {
        const float* Qg = g_qh + ((size_t)bh * Ss + q0) * Dd;
        const int r = tid >> 1;                 // 0..127
        const int cf = (tid & 1) * 32;          // float col base (32 floats)
        const unsigned arr = (r < 64) ? 0u : 2*AARR;   // Kh or Vh
        const int rr = r & 63;
        const unsigned rowb = sbase + arr + (unsigned)((rr*36 + (tid&1)*16) * 4);
        #pragma unroll
        for (int i = 0; i < 8; i++) {
            float4 x = *(const float4*)(Qg + (size_t)r*64 + cf + i*4);
            x.x *= QSCALE; x.y *= QSCALE; x.z *= QSCALE; x.w *= QSCALE;
            sts2(rowb + i*8,        packbf(x.x,x.y), packbf(x.z,x.w));
            sts2(rowb + i*8 + AARR, packbf(bferr(x.x),bferr(x.y)), packbf(bferr(x.z),bferr(x.w)));
        }
    }
    __syncthreads();

    // Q fragments (A operand): warp w owns q rows w*16..+15
    unsigned qh[4][4], ql[4][4];
    {
        const unsigned arr = (w < 4) ? 0u : 2*AARR;
        const int rr = (w*16) & 63;
        const int row = rr + ((lane>>3)&1)*8 + (lane&7);
        const unsigned off = (unsigned)((row*36 + ((lane>>4)<<2)) * 4);
        #pragma unroll
        for (int dt = 0; dt < 4; dt++) {
            ldsm4(sbase + arr        + off + dt*32, qh[dt]);
            ldsm4(sbase + arr + AARR + off + dt*32, ql[dt]);
        }
    }

    // prefetch tile 0
    const float* Kg0 = g_kh + (size_t)bh * Ss * Dd;
    const float* Vg0 = g_vt + (size_t)bh * Dd * Ss;
    const unsigned char* mp = mask + (size_t)b * Ss;

    const int r2 = tid >> 2, cf2 = (tid & 3) * 16;
    const float* Krp = Kg0 + (size_t)r2 * Dd + cf2;          // + kt*64*Dd
    const float* Vrp = Vg0 + (size_t)r2 * Ss + cf2;          // + kt*64

    float4 pk[4], pv[4];
    unsigned pmask = 0;
    #pragma unroll
    for (int i = 0; i < 4; i++) {
        pk[i] = *(const float4*)(Krp + i*4);
        pv[i] = *(const float4*)(Vrp + i*4);
    }
    if (tid < 64) pmask = mp[tid];
    __syncthreads();   // all warps done reading Q staging

    // ldmatrix offsets for K/V tiles (stride 36 u32)
    unsigned kvoff[4];
    #pragma unroll
    for (int np = 0; np < 4; np++) {
        int row = np*16 + ((lane>>4)&1)*8 + (lane&7);
        kvoff[np] = (unsigned)((row*36 + (((lane>>3)&1)<<2)) * 4);
    }
    const unsigned rowb2 = (unsigned)((r2*36 + (tid&3)*8) * 4);

    float O[8][4] = {};
    float l0 = 0.f, l1 = 0.f;

    for (int kt = 0; kt < Ss/64; kt++) {
        const unsigned sb = sbase + (unsigned)(kt & 1) * ASTG;
        // STS prefetch
        #pragma unroll
        for (int i = 0; i < 4; i++) {
            float4 x = pk[i], y = pv[i];
            unsigned off = sb + rowb2 + i*8;
            sts2(off + 0*AARR, packbf(x.x,x.y), packbf(x.z,x.w));
            sts2(off + 1*AARR, packbf(bferr(x.x),bferr(x.y)), packbf(bferr(x.z),bferr(x.w)));
            sts2(off + 2*AARR, packbf(y.x,y.y), packbf(y.z,y.w));
            sts2(off + 3*AARR, packbf(bferr(y.x),bferr(y.y)), packbf(bferr(y.z),bferr(y.w)));
        }
        if (tid < 64)
            ((float*)(smraw + AMSK + (kt&1)*256))[tid] = pmask ? -1e9f : 0.f;
        __syncthreads();

        if (kt + 1 < Ss/64) {
            #pragma unroll
            for (int i = 0; i < 4; i++) {
                pk[i] = *(const float4*)(Krp + (size_t)(kt+1)*64*Dd + i*4);
                pv[i] = *(const float4*)(Vrp + (kt+1)*64 + i*4);
            }
            if (tid < 64) pmask = mp[(kt+1)*64 + tid];
        }

        // scores S = (scaled Q) K^T  (bf16x3)
        float Sc[8][4] = {};
        #pragma unroll
        for (int dt = 0; dt < 4; dt++) {
            const unsigned kob = dt*32;
            #pragma unroll
            for (int np = 0; np < 4; np++) {
                unsigned kbh[4], kbl[4];
                ldsm4(sb + 0*AARR + kvoff[np] + kob, kbh);
                ldsm4(sb + 1*AARR + kvoff[np] + kob, kbl);
                #pragma unroll
                for (int hf = 0; hf < 2; hf++) {
                    const int nt = np*2 + hf;
                    mma16816(Sc[nt], qh[dt], kbh + hf*2);
                    mma16816(Sc[nt], qh[dt], kbl + hf*2);
                    mma16816(Sc[nt], ql[dt], kbh + hf*2);
                }
            }
        }

        // softmax (no max) + P fragments in-register
        const float* msk = (const float*)(smraw + AMSK + (kt&1)*256);
        unsigned pah[4][4], pal[4][4];
        #pragma unroll
        for (int nt = 0; nt < 8; nt++) {
            int j = nt*8 + t*2;
            float mv0 = msk[j], mv1 = msk[j+1];
            float p0 = exp2f(Sc[nt][0] + mv0);
            float p1 = exp2f(Sc[nt][1] + mv1);
            float p2 = exp2f(Sc[nt][2] + mv0);
            float p3 = exp2f(Sc[nt][3] + mv1);
            l0 += p0 + p1;
            l1 += p2 + p3;
            int kk = nt >> 1, hi = (nt & 1) * 2;
            pah[kk][hi]   = packbf(p0, p1);
            pah[kk][hi+1] = packbf(p2, p3);
            pal[kk][hi]   = packbf(bferr(p0), bferr(p1));
            pal[kk][hi+1] = packbf(bferr(p2), bferr(p3));
        }

        // O += P V  (bf16x3)
        #pragma unroll
        for (int kk = 0; kk < 4; kk++) {
            const unsigned kob = kk*32;
            #pragma unroll
            for (int np = 0; np < 4; np++) {
                unsigned vbh[4], vbl[4];
                ldsm4(sb + 2*AARR + kvoff[np] + kob, vbh);
                ldsm4(sb + 3*AARR + kvoff[np] + kob, vbl);
                #pragma unroll
                for (int hf = 0; hf < 2; hf++) {
                    const int nt = np*2 + hf;
                    mma16816(O[nt], pah[kk], vbh + hf*2);
                    mma16816(O[nt], pal[kk], vbh + hf*2);
                    mma16816(O[nt], pah[kk], vbl + hf*2);
                }
            }
        }
        // single sync per stage (next STS hits the other buffer)
    }

    #pragma unroll
    for (int off = 1; off < 4; off <<= 1) {
        l0 += __shfl_xor_sync(0xffffffffu, l0, off);
        l1 += __shfl_xor_sync(0xffffffffu, l1, off);
    }
    const float inv0 = 1.0f / l0, inv1 = 1.0f / l1;

    const int q = q0 + w*16 + g;
    float* d0 = g_ao + ((size_t)b * Ss + q) * Ee + h*64;
    float* d1 = g_ao + ((size_t)b * Ss + q + 8) * Ee + h*64;
    #pragma unroll
    for (int nt = 0; nt < 8; nt++) {
        int c = nt*8 + t*2;
        d0[c]   = O[nt][0] * inv0;
        d0[c+1] = O[nt][1] * inv0;
        d1[c]   = O[nt][2] * inv1;
        d1[c+1] = O[nt][3] * inv1;
    }
}

// ===========================================================================
extern "C" void kernel_launch(void* const* d_in, const int* in_sizes, int n_in,
                              void* d_out, int out_size)
{
    const float* q  = (const float*)d_in[0];
    const float* k  = (const float*)d_in[1];
    const float* v  = (const float*)d_in[2];
    const unsigned char* mask = (const unsigned char*)d_in[3];
    const float* Wq = (const float*)d_in[4];
    const float* bq = (const float*)d_in[5];
    const float* Wk = (const float*)d_in[6];
    const float* bk = (const float*)d_in[7];
    const float* Wv = (const float*)d_in[8];
    const float* bv = (const float*)d_in[9];
    const float* Wo = (const float*)d_in[10];
    const float* bo = (const float*)d_in[11];
    float* out = (float*)d_out;

    cudaFuncSetAttribute(qkv_mma,   cudaFuncAttributeMaxDynamicSharedMemorySize, GE_DYN);
    cudaFuncSetAttribute(oproj_mma, cudaFuncAttributeMaxDynamicSharedMemorySize, GE_DYN);
    cudaFuncSetAttribute(attn_mma,  cudaFuncAttributeMaxDynamicSharedMemorySize, AT_DYN);

    dim3 g1(Ee/128, Mrows/128, 3);
    qkv_mma<<<g1, 256, GE_DYN>>>(q, k, v, Wq, bq, Wk, bk, Wv, bv);

    dim3 g2(Ss/128, Bb*Hh);
    attn_mma<<<g2, 256, AT_DYN>>>(mask);

    dim3 g3(Ee/128, Mrows/128);
    oproj_mma<<<g3, 256, GE_DYN>>>(q, Wo, bo, out);
}

// round 9
// speedup vs baseline: 3.2980x; 1.1543x over previous
// MultiHead fused block: bf16x3 mma.sync + cp.async pipelines.
// Theory: qkv_mma was latency-bound (occ 12.5%, regs 163, in-loop packing).
// (1) conv_hilo pre-splits fp32 operands to persistent bf16 hi/lo planes;
// (2) GEMM BK=16 4-stage cp.async, 2 CTAs/SM; (3) attn 3-stage cp.async,
// Q pre-scaled 0.125*log2e, single exp2f softmax. Predict 772 -> ~500 us.
#include <cuda_runtime.h>
#include <cuda_bf16.h>

#define Bb 2
#define Ss 2048
#define Ee 1024
#define Hh 16
#define Dd 64
#define Mrows (Bb*Ss)
#define NHD ((size_t)Bb*Hh*Ss*Dd)

__device__ __nv_bfloat16 cA_h[3*(size_t)Mrows*Ee], cA_l[3*(size_t)Mrows*Ee];
__device__ __nv_bfloat16 cW_h[4*(size_t)Ee*Ee],    cW_l[4*(size_t)Ee*Ee];
__device__ __nv_bfloat16 g_qh_h[NHD], g_qh_l[NHD];   // [B,H,S,D], pre-scaled
__device__ __nv_bfloat16 g_kh_h[NHD], g_kh_l[NHD];   // [B,H,S,D]
__device__ __nv_bfloat16 g_vt_h[NHD], g_vt_l[NHD];   // [B,H,D,S]
__device__ __nv_bfloat16 g_ao_h[(size_t)Mrows*Ee], g_ao_l[(size_t)Mrows*Ee];

__device__ __forceinline__ unsigned smem_u32(const void* p){
    unsigned a;
    asm("{ .reg .u64 t; cvta.to.shared.u64 t, %1; cvt.u32.u64 %0, t; }"
        : "=r"(a) : "l"(p));
    return a;
}
__device__ __forceinline__ unsigned packbf(float e0, float e1){
    unsigned r;   // lo half = e0, hi half = e1
    asm("cvt.rn.bf16x2.f32 %0, %1, %2;" : "=r"(r) : "f"(e1), "f"(e0));
    return r;
}
__device__ __forceinline__ float bferr(float x){
    __nv_bfloat16 h = __float2bfloat16(x);
    return x - __bfloat162float(h);
}
__device__ __forceinline__ void mma16816(float* d, const unsigned* a, const unsigned* b){
    asm volatile(
        "mma.sync.aligned.m16n8k16.row.col.f32.bf16.bf16.f32 "
        "{%0,%1,%2,%3}, {%4,%5,%6,%7}, {%8,%9}, {%0,%1,%2,%3};"
        : "+f"(d[0]), "+f"(d[1]), "+f"(d[2]), "+f"(d[3])
        : "r"(a[0]), "r"(a[1]), "r"(a[2]), "r"(a[3]), "r"(b[0]), "r"(b[1]));
}
__device__ __forceinline__ void ldsm4(unsigned addr, unsigned* r){
    asm volatile("ldmatrix.sync.aligned.m8n8.x4.shared.b16 {%0,%1,%2,%3}, [%4];"
                 : "=r"(r[0]), "=r"(r[1]), "=r"(r[2]), "=r"(r[3]) : "r"(addr));
}
__device__ __forceinline__ void cp16(unsigned dst, const void* src){
    asm volatile("cp.async.cg.shared.global [%0], [%1], 16;"
                 :: "r"(dst), "l"(__cvta_generic_to_global(src)) : "memory");
}
#define CP_COMMIT() asm volatile("cp.async.commit_group;" ::: "memory")
#define CP_WAIT(n)  asm volatile("cp.async.wait_group %0;" :: "n"(n) : "memory")

// ---------------------------------------------------------------------------
// Convert fp32 -> bf16 hi/lo planes. z=0..2 inputs, z=3..6 weights.
// ---------------------------------------------------------------------------
__global__ __launch_bounds__(256) void conv_hilo(
    const float* __restrict__ q, const float* __restrict__ k,
    const float* __restrict__ v,
    const float* __restrict__ Wq, const float* __restrict__ Wk,
    const float* __restrict__ Wv, const float* __restrict__ Wo)
{
    const int z = blockIdx.z;
    const float* src; __nv_bfloat16 *dh, *dl; size_t n;
    if (z < 3) {
        src = (z == 0) ? q : (z == 1) ? k : v;
        dh = cA_h + (size_t)z * Mrows * Ee;
        dl = cA_l + (size_t)z * Mrows * Ee;
        n = (size_t)Mrows * Ee;
    } else {
        src = (z == 3) ? Wq : (z == 4) ? Wk : (z == 5) ? Wv : Wo;
        dh = cW_h + (size_t)(z - 3) * Ee * Ee;
        dl = cW_l + (size_t)(z - 3) * Ee * Ee;
        n = (size_t)Ee * Ee;
    }
    size_t i = ((size_t)blockIdx.x * 256 + threadIdx.x) * 4;
    if (i >= n) return;
    float4 x = *(const float4*)(src + i);
    *(unsigned*)&dh[i]   = packbf(x.x, x.y);
    *(unsigned*)&dh[i+2] = packbf(x.z, x.w);
    *(unsigned*)&dl[i]   = packbf(bferr(x.x), bferr(x.y));
    *(unsigned*)&dl[i+2] = packbf(bferr(x.z), bferr(x.w));
}

// ---------------------------------------------------------------------------
// GEMM core: 128x128 CTA, BK=16, 4-stage cp.async, 256 thr, 8 warps (4m x 2n),
// warp tile 32x64, bf16x3. Smem row stride 12 u32 (48B).
// ---------------------------------------------------------------------------
#define GPL 6144
#define GST (4*GPL)
#define GE_DYN (4*GST)

__device__ __forceinline__ void gemm_tc(float acc[2][8][4],
        const __nv_bfloat16* __restrict__ Agh, const __nv_bfloat16* __restrict__ Agl,
        const __nv_bfloat16* __restrict__ Bgh, const __nv_bfloat16* __restrict__ Bgl,
        unsigned sbase, int tid)
{
    const int lane = tid & 31, wid = tid >> 5;
    const int wm = (wid & 3) * 32, wn = (wid >> 2) * 64;

    const int r = tid >> 1, ch = tid & 1;
    const __nv_bfloat16* pAh = Agh + (size_t)r * Ee + ch * 8;
    const __nv_bfloat16* pAl = Agl + (size_t)r * Ee + ch * 8;
    const __nv_bfloat16* pBh = Bgh + (size_t)r * Ee + ch * 8;
    const __nv_bfloat16* pBl = Bgl + (size_t)r * Ee + ch * 8;
    const unsigned drow = (unsigned)(r * 48 + ch * 16);

    unsigned aoff[2];
    #pragma unroll
    for (int mt = 0; mt < 2; mt++) {
        int row = wm + mt*16 + ((lane>>3)&1)*8 + (lane&7);
        aoff[mt] = (unsigned)((row*12 + ((lane>>4)<<2)) * 4);
    }
    unsigned boff[4];
    #pragma unroll
    for (int np = 0; np < 4; np++) {
        int row = wn + np*16 + ((lane>>4)&1)*8 + (lane&7);
        boff[np] = (unsigned)((row*12 + (((lane>>3)&1)<<2)) * 4);
    }

    #pragma unroll
    for (int st = 0; st < 3; st++) {
        unsigned sb = sbase + st*GST;
        cp16(sb + drow,         pAh + st*16);
        cp16(sb + GPL + drow,   pAl + st*16);
        cp16(sb + 2*GPL + drow, pBh + st*16);
        cp16(sb + 3*GPL + drow, pBl + st*16);
        CP_COMMIT();
    }

    for (int s = 0; s < Ee/16; s++) {
        CP_WAIT(2);
        __syncthreads();
        const unsigned sb = sbase + (unsigned)(s & 3) * GST;

        unsigned ah[2][4], al[2][4];
        ldsm4(sb + aoff[0], ah[0]);        ldsm4(sb + GPL + aoff[0], al[0]);
        ldsm4(sb + aoff[1], ah[1]);        ldsm4(sb + GPL + aoff[1], al[1]);
        #pragma unroll
        for (int np = 0; np < 4; np++) {
            unsigned bh[4], bl[4];
            ldsm4(sb + 2*GPL + boff[np], bh);
            ldsm4(sb + 3*GPL + boff[np], bl);
            #pragma unroll
            for (int hf = 0; hf < 2; hf++) {
                const int nt = np*2 + hf;
                #pragma unroll
                for (int mt = 0; mt < 2; mt++) {
                    mma16816(acc[mt][nt], ah[mt], bh + hf*2);
                    mma16816(acc[mt][nt], ah[mt], bl + hf*2);
                    mma16816(acc[mt][nt], al[mt], bh + hf*2);
                }
            }
        }
        if (s + 3 < Ee/16) {
            const int k0 = (s + 3) * 16;
            unsigned sb2 = sbase + (unsigned)((s + 3) & 3) * GST;
            cp16(sb2 + drow,         pAh + k0);
            cp16(sb2 + GPL + drow,   pAl + k0);
            cp16(sb2 + 2*GPL + drow, pBh + k0);
            cp16(sb2 + 3*GPL + drow, pBl + k0);
        }
        CP_COMMIT();
    }
}

// ---------------------------------------------------------------------------
// QKV projection; writes bf16 hi/lo planes (Q pre-scaled by 0.125*log2e).
// ---------------------------------------------------------------------------
__global__ __launch_bounds__(256, 2) void qkv_mma(
    const float* __restrict__ bq, const float* __restrict__ bk,
    const float* __restrict__ bv)
{
    extern __shared__ char smraw[];
    unsigned sbase = smem_u32(smraw);
    const int tid = threadIdx.x;
    const int z = blockIdx.z;
    const int m0 = blockIdx.y * 128, n0 = blockIdx.x * 128;
    const float* bias = (z == 0) ? bq : (z == 1) ? bk : bv;

    float acc[2][8][4] = {};
    gemm_tc(acc,
            cA_h + ((size_t)z*Mrows + m0)*Ee, cA_l + ((size_t)z*Mrows + m0)*Ee,
            cW_h + ((size_t)z*Ee + n0)*Ee,    cW_l + ((size_t)z*Ee + n0)*Ee,
            sbase, tid);

    const int lane = tid & 31, wid = tid >> 5;
    const int g = lane >> 2, t = lane & 3;
    const int wm = (wid & 3) * 32, wn = (wid >> 2) * 64;
    const float QSCALE = 0.125f * 1.4426950408889634f;

    #pragma unroll
    for (int mt = 0; mt < 2; mt++) {
        #pragma unroll
        for (int nt = 0; nt < 8; nt++) {
            int m = m0 + wm + mt*16 + g;
            int n = n0 + wn + nt*8 + t*2;
            float b0v = bias[n], b1v = bias[n+1];
            int b = m >> 11, s = m & 2047;
            int h = n >> 6, d = n & 63;
            float v00 = acc[mt][nt][0] + b0v, v01 = acc[mt][nt][1] + b1v;
            float v10 = acc[mt][nt][2] + b0v, v11 = acc[mt][nt][3] + b1v;
            if (z == 0) {
                v00 *= QSCALE; v01 *= QSCALE; v10 *= QSCALE; v11 *= QSCALE;
                size_t i0 = (((size_t)(b*Hh + h))*Ss + s)*Dd + d;
                *(unsigned*)&g_qh_h[i0] = packbf(v00, v01);
                *(unsigned*)&g_qh_l[i0] = packbf(bferr(v00), bferr(v01));
                size_t i1 = i0 + 8*Dd;
                *(unsigned*)&g_qh_h[i1] = packbf(v10, v11);
                *(unsigned*)&g_qh_l[i1] = packbf(bferr(v10), bferr(v11));
            } else if (z == 1) {
                size_t i0 = (((size_t)(b*Hh + h))*Ss + s)*Dd + d;
                *(unsigned*)&g_kh_h[i0] = packbf(v00, v01);
                *(unsigned*)&g_kh_l[i0] = packbf(bferr(v00), bferr(v01));
                size_t i1 = i0 + 8*Dd;
                *(unsigned*)&g_kh_h[i1] = packbf(v10, v11);
                *(unsigned*)&g_kh_l[i1] = packbf(bferr(v10), bferr(v11));
            } else {
                size_t i0 = (((size_t)(b*Hh + h))*Dd + d)*Ss + s;
                g_vt_h[i0]      = __float2bfloat16(v00);
                g_vt_l[i0]      = __float2bfloat16(bferr(v00));
                g_vt_h[i0+Ss]   = __float2bfloat16(v01);
                g_vt_l[i0+Ss]   = __float2bfloat16(bferr(v01));
                g_vt_h[i0+8]    = __float2bfloat16(v10);
                g_vt_l[i0+8]    = __float2bfloat16(bferr(v10));
                g_vt_h[i0+Ss+8] = __float2bfloat16(v11);
                g_vt_l[i0+Ss+8] = __float2bfloat16(bferr(v11));
            }
        }
    }
}

// ---------------------------------------------------------------------------
// Output projection + bias + residual (fp32 out)
// ---------------------------------------------------------------------------
__global__ __launch_bounds__(256, 2) void oproj_mma(
    const float* __restrict__ qin, const float* __restrict__ bo,
    float* __restrict__ out)
{
    extern __shared__ char smraw[];
    unsigned sbase = smem_u32(smraw);
    const int tid = threadIdx.x;
    const int m0 = blockIdx.y * 128, n0 = blockIdx.x * 128;

    float acc[2][8][4] = {};
    gemm_tc(acc,
            g_ao_h + (size_t)m0*Ee, g_ao_l + (size_t)m0*Ee,
            cW_h + ((size_t)3*Ee + n0)*Ee, cW_l + ((size_t)3*Ee + n0)*Ee,
            sbase, tid);

    const int lane = tid & 31, wid = tid >> 5;
    const int g = lane >> 2, t = lane & 3;
    const int wm = (wid & 3) * 32, wn = (wid >> 2) * 64;

    #pragma unroll
    for (int mt = 0; mt < 2; mt++) {
        #pragma unroll
        for (int nt = 0; nt < 8; nt++) {
            int m = m0 + wm + mt*16 + g;
            int n = n0 + wn + nt*8 + t*2;
            float b0v = bo[n], b1v = bo[n+1];
            size_t i0 = (size_t)m * Ee + n;
            size_t i1 = (size_t)(m+8) * Ee + n;
            out[i0]   = acc[mt][nt][0] + b0v + qin[i0];
            out[i0+1] = acc[mt][nt][1] + b1v + qin[i0+1];
            out[i1]   = acc[mt][nt][2] + b0v + qin[i1];
            out[i1+1] = acc[mt][nt][3] + b1v + qin[i1+1];
        }
    }
}

// ---------------------------------------------------------------------------
// Flash attention: 3-stage cp.async K/V pipeline, no-max softmax, bf16x3.
// CTA = (b,h) x 128 queries, 256 threads. Smem rows 144B stride, 64 rows per
// plane, 4 planes (Kh,Kl,Vh,Vl) per stage. Q staged once at start.
// ---------------------------------------------------------------------------
#define APL 9216
#define AST (4*APL)
#define AMSK (3*AST)
#define AT_DYN (AMSK + 2048)

__global__ __launch_bounds__(256, 1) void attn_mma(const unsigned char* __restrict__ mask)
{
    extern __shared__ char smraw[];
    unsigned sbase = smem_u32(smraw);
    const int tid = threadIdx.x;
    const int lane = tid & 31, w = tid >> 5;
    const int g = lane >> 2, t = lane & 3;
    const int bh = blockIdx.y, b = bh >> 4, h = bh & 15;
    const int q0 = blockIdx.x * 128;

    ((unsigned long long*)(smraw + AMSK))[tid] =
        ((const unsigned long long*)(mask + (size_t)b * Ss))[tid];

    // Q staging: 128 rows x 64 bf16 (128B/row) at 144B stride; hi in plane 0/1,
    // lo in plane 2/3 region of stage 0 (rows 0..63 plane0, 64..127 plane1).
    {
        const __nv_bfloat16* Qh = g_qh_h + ((size_t)bh * Ss + q0) * Dd;
        const __nv_bfloat16* Ql = g_qh_l + ((size_t)bh * Ss + q0) * Dd;
        const int qr = tid >> 1;
        const int qc = (tid & 1) * 4;
        const unsigned hiplane = (qr >= 64) ? (unsigned)APL : 0u;
        unsigned qdst = sbase + hiplane + (unsigned)((qr & 63) * 144 + qc * 16);
        #pragma unroll
        for (int i = 0; i < 4; i++) {
            cp16(qdst + i*16,         Qh + (size_t)qr*64 + (qc+i)*8);
            cp16(qdst + 2*APL + i*16, Ql + (size_t)qr*64 + (qc+i)*8);
        }
        CP_COMMIT();
        CP_WAIT(0);
        __syncthreads();
    }

    unsigned qfh[4][4], qfl[4][4];
    {
        const int rowfull = w*16 + ((lane>>3)&1)*8 + (lane&7);
        const unsigned hiplane = (rowfull >= 64) ? (unsigned)APL : 0u;
        const unsigned off = hiplane + (unsigned)(((rowfull & 63)*36 + ((lane>>4)<<2)) * 4);
        #pragma unroll
        for (int dt = 0; dt < 4; dt++) {
            ldsm4(sbase + off + dt*32,         qfh[dt]);
            ldsm4(sbase + 2*APL + off + dt*32, qfl[dt]);
        }
    }
    __syncthreads();

    const __nv_bfloat16* Kh_g = g_kh_h + (size_t)bh * Ss * Dd;
    const __nv_bfloat16* Kl_g = g_kh_l + (size_t)bh * Ss * Dd;
    const __nv_bfloat16* Vh_g = g_vt_h + (size_t)bh * Dd * Ss;
    const __nv_bfloat16* Vl_g = g_vt_l + (size_t)bh * Dd * Ss;

    const int r2 = tid >> 2;
    const int cb = (tid & 3) * 2;
    const unsigned drow = (unsigned)(r2 * 144 + cb * 16);
    const __nv_bfloat16* pKh = Kh_g + (size_t)r2 * Dd + cb * 8;
    const __nv_bfloat16* pKl = Kl_g + (size_t)r2 * Dd + cb * 8;
    const __nv_bfloat16* pVh = Vh_g + (size_t)r2 * Ss + cb * 8;
    const __nv_bfloat16* pVl = Vl_g + (size_t)r2 * Ss + cb * 8;

    #pragma unroll
    for (int st = 0; st < 2; st++) {
        unsigned sb = sbase + st*AST;
        #pragma unroll
        for (int i = 0; i < 2; i++) {
            cp16(sb + drow + i*16,         pKh + (size_t)st*64*Dd + i*8);
            cp16(sb + APL + drow + i*16,   pKl + (size_t)st*64*Dd + i*8);
            cp16(sb + 2*APL + drow + i*16, pVh + st*64 + i*8);
            cp16(sb + 3*APL + drow + i*16, pVl + st*64 + i*8);
        }
        CP_COMMIT();
    }

    unsigned kvoff[4];
    #pragma unroll
    for (int np = 0; np < 4; np++) {
        int row = np*16 + ((lane>>4)&1)*8 + (lane&7);
        kvoff[np] = (unsigned)((row*36 + (((lane>>3)&1)<<2)) * 4);
    }

    const unsigned char* mb = (const unsigned char*)(smraw + AMSK);
    float O[8][4] = {};
    float l0 = 0.f, l1 = 0.f;

    for (int kt = 0; kt < Ss/64; kt++) {
        CP_WAIT(1);
        __syncthreads();
        const unsigned sb = sbase + (unsigned)(kt % 3) * AST;

        float Sc[8][4] = {};
        #pragma unroll
        for (int dt = 0; dt < 4; dt++) {
            const unsigned kob = dt*32;
            #pragma unroll
            for (int np = 0; np < 4; np++) {
                unsigned kbh[4], kbl[4];
                ldsm4(sb + kvoff[np] + kob, kbh);
                ldsm4(sb + APL + kvoff[np] + kob, kbl);
                #pragma unroll
                for (int hf = 0; hf < 2; hf++) {
                    const int nt = np*2 + hf;
                    mma16816(Sc[nt], qfh[dt], kbh + hf*2);
                    mma16816(Sc[nt], qfh[dt], kbl + hf*2);
                    mma16816(Sc[nt], qfl[dt], kbh + hf*2);
                }
            }
        }

        unsigned pah[4][4], pal[4][4];
        #pragma unroll
        for (int nt = 0; nt < 8; nt++) {
            int j = kt*64 + nt*8 + t*2;
            float mv0 = mb[j]   ? -1e9f : 0.f;
            float mv1 = mb[j+1] ? -1e9f : 0.f;
            float p0 = exp2f(Sc[nt][0] + mv0);
            float p1 = exp2f(Sc[nt][1] + mv1);
            float p2 = exp2f(Sc[nt][2] + mv0);
            float p3 = exp2f(Sc[nt][3] + mv1);
            l0 += p0 + p1;
            l1 += p2 + p3;
            int kk = nt >> 1, hi = (nt & 1) * 2;
            pah[kk][hi]   = packbf(p0, p1);
            pah[kk][hi+1] = packbf(p2, p3);
            pal[kk][hi]   = packbf(bferr(p0), bferr(p1));
            pal[kk][hi+1] = packbf(bferr(p2), bferr(p3));
        }

        #pragma unroll
        for (int kk = 0; kk < 4; kk++) {
            const unsigned kob = kk*32;
            #pragma unroll
            for (int np = 0; np < 4; np++) {
                unsigned vbh[4], vbl[4];
                ldsm4(sb + 2*APL + kvoff[np] + kob, vbh);
                ldsm4(sb + 3*APL + kvoff[np] + kob, vbl);
                #pragma unroll
                for (int hf = 0; hf < 2; hf++) {
                    const int nt = np*2 + hf;
                    mma16816(O[nt], pah[kk], vbh + hf*2);
                    mma16816(O[nt], pal[kk], vbh + hf*2);
                    mma16816(O[nt], pah[kk], vbl + hf*2);
                }
            }
        }

        if (kt + 2 < Ss/64) {
            const int kn = kt + 2;
            unsigned sb2 = sbase + (unsigned)(kn % 3) * AST;
            #pragma unroll
            for (int i = 0; i < 2; i++) {
                cp16(sb2 + drow + i*16,         pKh + (size_t)kn*64*Dd + i*8);
                cp16(sb2 + APL + drow + i*16,   pKl + (size_t)kn*64*Dd + i*8);
                cp16(sb2 + 2*APL + drow + i*16, pVh + kn*64 + i*8);
                cp16(sb2 + 3*APL + drow + i*16, pVl + kn*64 + i*8);
            }
        }
        CP_COMMIT();
    }

    #pragma unroll
    for (int off = 1; off < 4; off <<= 1) {
        l0 += __shfl_xor_sync(0xffffffffu, l0, off);
        l1 += __shfl_xor_sync(0xffffffffu, l1, off);
    }
    const float inv0 = 1.0f / l0, inv1 = 1.0f / l1;

    const int q = q0 + w*16 + g;
    size_t base0 = ((size_t)b * Ss + q) * Ee + h*64;
    size_t base1 = ((size_t)b * Ss + q + 8) * Ee + h*64;
    #pragma unroll
    for (int nt = 0; nt < 8; nt++) {
        int c = nt*8 + t*2;
        float v0 = O[nt][0] * inv0, v1 = O[nt][1] * inv0;
        float v2 = O[nt][2] * inv1, v3 = O[nt][3] * inv1;
        *(unsigned*)&g_ao_h[base0 + c] = packbf(v0, v1);
        *(unsigned*)&g_ao_l[base0 + c] = packbf(bferr(v0), bferr(v1));
        *(unsigned*)&g_ao_h[base1 + c] = packbf(v2, v3);
        *(unsigned*)&g_ao_l[base1 + c] = packbf(bferr(v2), bferr(v3));
    }
}

extern "C" void kernel_launch(void* const* d_in, const int* in_sizes, int n_in,
                              void* d_out, int out_size)
{
    const float* q  = (const float*)d_in[0];
    const float* k  = (const float*)d_in[1];
    const float* v  = (const float*)d_in[2];
    const unsigned char* mask = (const unsigned char*)d_in[3];
    const float* Wq = (const float*)d_in[4];
    const float* bq = (const float*)d_in[5];
    const float* Wk = (const float*)d_in[6];
    const float* bk = (const float*)d_in[7];
    const float* Wv = (const float*)d_in[8];
    const float* bv = (const float*)d_in[9];
    const float* Wo = (const float*)d_in[10];
    const float* bo = (const float*)d_in[11];
    float* out = (float*)d_out;

    cudaFuncSetAttribute(qkv_mma,   cudaFuncAttributeMaxDynamicSharedMemorySize, GE_DYN);
    cudaFuncSetAttribute(oproj_mma, cudaFuncAttributeMaxDynamicSharedMemorySize, GE_DYN);
    cudaFuncSetAttribute(attn_mma,  cudaFuncAttributeMaxDynamicSharedMemorySize, AT_DYN);

    dim3 gc((Mrows*Ee/4 + 255)/256, 1, 7);
    conv_hilo<<<gc, 256>>>(q, k, v, Wq, Wk, Wv, Wo);

    dim3 g1(Ee/128, Mrows/128, 3);
    qkv_mma<<<g1, 256, GE_DYN>>>(bq, bk, bv);

    dim3 g2(Ss/128, Bb*Hh);
    attn_mma<<<g2, 256, AT_DYN>>>(mask);

    dim3 g3(Ee/128, Mrows/128);
    oproj_mma<<<g3, 256, GE_DYN>>>(q, bo, out);
}